// round 16
// baseline (speedup 1.0000x reference)
#include <cuda_runtime.h>
#include <cstdint>

// out[c,t,x,y] = mc ? k[t] : mp ? 0.5*k[t-1] : mn ? 0.25*k[t+1] : 0   (cases exclusive)
// Mask is channel-invariant. Kernel 1 (pre): per (h, g) thread walks
// t = 8h..8h+7 with rolling mask AND rolling channel-0 k registers,
// packing the 2-bit selector words into the 1 MB L2-resident word-major
// table AND writing out[c=0] directly. Kernel 2 (dsb): pure rolling
// 1-load/1-store stream for channels 1..31 (512-thread CTAs, 8 KB
// contiguous per t-access, 32 regs).

#define ALPHA 0.5f
#define BETA  0.25f

constexpr int NC  = 32;
constexpr int NT  = 64;
constexpr int PLANE4 = 256 * 256 / 4;    // 16384 float4 groups per t-slice
constexpr int NW     = NT / 4;           // 16 selector words per g
constexpr int TPB    = 512;              // stream CTA size
constexpr int COLS31 = (NC - 1) * PLANE4;   // 507904 stream threads (c=1..31)
constexpr int NCTA   = COLS31 / TPB;     // 992

__device__ uint32_t g_sel[NW * PLANE4];  // [word w][g], 1 MB

__device__ __forceinline__ uint32_t code1(int mc, int mp, int mn) {
    return mc ? 1u : (mp ? 2u : (mn ? 3u : 0u));
}

__device__ __forceinline__ float pick(uint32_t c, float kc, float kp, float kn) {
    return (c == 1u) ? kc
         : (c == 2u) ? ALPHA * kp
         : (c == 3u) ? BETA * kn
         : 0.0f;
}

__device__ __forceinline__ float4 pick4(uint32_t byte, float4 kc, float4 kp, float4 kn) {
    float4 o;
    o.x = pick( byte       & 3u, kc.x, kp.x, kn.x);
    o.y = pick((byte >> 2) & 3u, kc.y, kp.y, kn.y);
    o.z = pick((byte >> 4) & 3u, kc.z, kp.z, kn.z);
    o.w = pick((byte >> 6) & 3u, kc.w, kp.w, kn.w);
    return o;
}

// One thread per (h, g), h = 0..7: t = 8h..8h+7.
// Rolling mask (10 loads) + rolling c=0 k (10 loads); emits 8 out stores
// (channel 0) + 2 selector words.
__global__ void __launch_bounds__(256)
pre_kernel(const float4* __restrict__ k,
           const int4*   __restrict__ mask,
           float4*       __restrict__ out)
{
    const int tidg = blockIdx.x * blockDim.x + threadIdx.x;  // 0 .. 8*PLANE4-1
    const int g = tidg & (PLANE4 - 1);
    const int h = tidg >> 14;            // 0..7
    const int t0 = h * 8;

    const float4 zero4 = make_float4(0.f, 0.f, 0.f, 0.f);

    int4   mp = (t0 > 0) ? __ldg(&mask[(t0 - 1) * PLANE4 + g]) : make_int4(0, 0, 0, 0);
    int4   mc = __ldg(&mask[t0 * PLANE4 + g]);
    float4 kp = (t0 > 0) ? __ldcs(&k[(t0 - 1) * PLANE4 + g]) : zero4;
    float4 kc = __ldcs(&k[t0 * PLANE4 + g]);

    uint32_t w[2] = {0u, 0u};

    #pragma unroll
    for (int i = 0; i < 8; i++) {
        const int t = t0 + i;
        int4   mn;
        float4 kn;
        if (t < NT - 1) {
            mn = __ldg(&mask[(t + 1) * PLANE4 + g]);
            kn = __ldcs(&k[(t + 1) * PLANE4 + g]);
        } else {
            mn = make_int4(0, 0, 0, 0);
            kn = zero4;
        }

        const uint32_t byte =  code1(mc.x, mp.x, mn.x)
                            | (code1(mc.y, mp.y, mn.y) << 2)
                            | (code1(mc.z, mp.z, mn.z) << 4)
                            | (code1(mc.w, mp.w, mn.w) << 6);
        w[i >> 2] |= byte << ((i & 3) * 8);

        __stcs(&out[t * PLANE4 + g], pick4(byte, kc, kp, kn));   // channel 0

        mp = mc; mc = mn;
        kp = kc; kc = kn;
    }

    g_sel[(2 * h)     * PLANE4 + g] = w[0];   // coalesced 4B stores
    g_sel[(2 * h + 1) * PLANE4 + g] = w[1];
}

__global__ void __launch_bounds__(TPB, 4)
dsb_kernel(const float4* __restrict__ k, float4* __restrict__ out)
{
    const int gid = blockIdx.x * TPB + threadIdx.x;
    const int g = gid & (PLANE4 - 1);
    const int c = 1 + (gid >> 14);       // channels 1..31

    const float4* kk = k   + (size_t)c * NT * PLANE4 + g;
    float4*       oo = out + (size_t)c * NT * PLANE4 + g;

    float4 kp = make_float4(0.f, 0.f, 0.f, 0.f);
    float4 kc = __ldcs(kk);

    int t = 0;
    #pragma unroll 1
    for (int w = 0; w < NW; w++) {
        const uint32_t wrd = __ldg(&g_sel[w * PLANE4 + g]);   // L2-resident
        #pragma unroll
        for (int tt = 0; tt < 4; tt++) {
            float4 kn = (t < NT - 1) ? __ldcs(kk + (t + 1) * PLANE4)
                                     : make_float4(0.f, 0.f, 0.f, 0.f);

            const uint32_t byte = (wrd >> (tt * 8)) & 0xFFu;
            __stcs(oo + t * PLANE4, pick4(byte, kc, kp, kn));

            kp = kc; kc = kn;
            t++;
        }
    }
}

extern "C" void kernel_launch(void* const* d_in, const int* in_sizes, int n_in,
                              void* d_out, int out_size)
{
    const float4* k    = (const float4*)d_in[0];
    const int4*   mask = (const int4*)d_in[1];
    float4*       out  = (float4*)d_out;

    pre_kernel<<<(8 * PLANE4) / 256, 256>>>(k, mask, out);
    dsb_kernel<<<NCTA, TPB>>>(k, out);
}